// round 1
// baseline (speedup 1.0000x reference)
#include <cuda_runtime.h>
#include <math.h>

#define BATCH  4
#define SEQ    4096
#define DMODEL 1024
#define DINNER 2048
#define DSTATE 16
#define NTOK   (BATCH*SEQ)     // 16384
#define CHUNK  128
#define NCHUNK (SEQ/CHUNK)     // 32

// ---- scratch (device globals; no allocations allowed) ----
__device__ float g_xmain[(size_t)NTOK*DINNER];
__device__ float g_sres [(size_t)NTOK*DINNER];
__device__ float g_xc   [(size_t)NTOK*DINNER];
__device__ float g_y    [(size_t)NTOK*DINNER];
__device__ float g_B    [NTOK*DSTATE];
__device__ float g_C    [NTOK*DSTATE];
__device__ float g_loc  [NTOK*DSTATE];
__device__ float g_E    [BATCH*NCHUNK*DSTATE];
__device__ float g_Sinit[BATCH*NCHUNK*DSTATE];
__device__ float g_ys   [NTOK];
__device__ float g_decay[DSTATE];

__device__ __forceinline__ float silu(float v) { return v / (1.f + expf(-v)); }

// ============================================================================
// SGEMM: 128x128 blocktile, BK=16, 256 threads, 8x8 per thread.
// MODE 0: A = x (param), C split -> g_xmain (cols<DINNER), g_sres=silu (cols>=DINNER)
// MODE 1: A = g_y (global), C -> out param
// ============================================================================
template<int MODE>
__global__ __launch_bounds__(256) void sgemm_kernel(
    const float* __restrict__ Ap, const float* __restrict__ Bm,
    float* __restrict__ Cp, int M, int N, int K)
{
    __shared__ float As[16][128];
    __shared__ float Bs[16][128];

    const float* A = (MODE == 1) ? (const float*)g_y : Ap;

    int tid = threadIdx.x;
    int bx = blockIdx.x, by = blockIdx.y;
    const int tx = tid & 15, ty = tid >> 4;

    float acc[8][8];
    #pragma unroll
    for (int i = 0; i < 8; i++)
        #pragma unroll
        for (int j = 0; j < 8; j++) acc[i][j] = 0.f;

    const int arow = tid >> 2;            // 0..63
    const int acol = (tid & 3) << 2;      // 0,4,8,12
    const int brow = tid >> 5;            // 0..7
    const int bcol = (tid & 31) << 2;     // 0..124

    const float* Ablk = A + (size_t)by * 128 * K;
    const float* Bblk = Bm + bx * 128;

    for (int kt = 0; kt < K; kt += 16) {
        #pragma unroll
        for (int r = 0; r < 128; r += 64) {
            float4 v = *(const float4*)(Ablk + (size_t)(arow + r) * K + kt + acol);
            As[acol + 0][arow + r] = v.x;
            As[acol + 1][arow + r] = v.y;
            As[acol + 2][arow + r] = v.z;
            As[acol + 3][arow + r] = v.w;
        }
        #pragma unroll
        for (int r = 0; r < 16; r += 8) {
            float4 v = *(const float4*)(Bblk + (size_t)(kt + brow + r) * N + bcol);
            *(float4*)(&Bs[brow + r][bcol]) = v;
        }
        __syncthreads();

        #pragma unroll
        for (int k = 0; k < 16; k++) {
            float ra[8], rb[8];
            #pragma unroll
            for (int i = 0; i < 8; i++) ra[i] = As[k][ty * 8 + i];
            #pragma unroll
            for (int j = 0; j < 8; j++) rb[j] = Bs[k][tx * 8 + j];
            #pragma unroll
            for (int i = 0; i < 8; i++)
                #pragma unroll
                for (int j = 0; j < 8; j++)
                    acc[i][j] += ra[i] * rb[j];
        }
        __syncthreads();
    }

    int row0 = by * 128 + ty * 8;
    int col0 = bx * 128 + tx * 8;
    #pragma unroll
    for (int i = 0; i < 8; i++) {
        #pragma unroll
        for (int j = 0; j < 8; j++) {
            float v = acc[i][j];
            int row = row0 + i, col = col0 + j;
            if (MODE == 0) {
                if (col < DINNER)
                    g_xmain[(size_t)row * DINNER + col] = v;
                else
                    g_sres[(size_t)row * DINNER + (col - DINNER)] = silu(v);
            } else {
                Cp[(size_t)row * N + col] = v;
            }
        }
    }
}

// ============================================================================
// Depthwise conv(3, pad 1) + bias + SiLU, then B/C projections (2048 -> 16)
// One block per token, 256 threads, 8 channels per thread.
// ============================================================================
__global__ __launch_bounds__(256) void conv_proj_kernel(
    const float* __restrict__ cw, const float* __restrict__ cb,
    const float* __restrict__ WB, const float* __restrict__ WC)
{
    int t = blockIdx.x;
    int l = t & (SEQ - 1);
    int tid = threadIdx.x;

    float accB[16], accC[16];
    #pragma unroll
    for (int s = 0; s < 16; s++) { accB[s] = 0.f; accC[s] = 0.f; }

    const float* xm = g_xmain + (size_t)t * DINNER;
    float* xcout = g_xc + (size_t)t * DINNER;

    for (int i = tid; i < DINNER; i += 256) {
        float w0 = cw[i * 3 + 0], w1 = cw[i * 3 + 1], w2 = cw[i * 3 + 2];
        float v = cb[i] + xm[i] * w1;
        if (l > 0)       v += xm[i - DINNER] * w0;
        if (l < SEQ - 1) v += xm[i + DINNER] * w2;
        float xc = silu(v);
        xcout[i] = xc;

        const float4* wb = (const float4*)(WB + (size_t)i * DSTATE);
        const float4* wc = (const float4*)(WC + (size_t)i * DSTATE);
        #pragma unroll
        for (int q = 0; q < 4; q++) {
            float4 b4 = wb[q], c4 = wc[q];
            accB[q * 4 + 0] += xc * b4.x;
            accB[q * 4 + 1] += xc * b4.y;
            accB[q * 4 + 2] += xc * b4.z;
            accB[q * 4 + 3] += xc * b4.w;
            accC[q * 4 + 0] += xc * c4.x;
            accC[q * 4 + 1] += xc * c4.y;
            accC[q * 4 + 2] += xc * c4.z;
            accC[q * 4 + 3] += xc * c4.w;
        }
    }

    // warp reduce each accumulator
    #pragma unroll
    for (int s = 0; s < 16; s++) {
        #pragma unroll
        for (int o = 16; o > 0; o >>= 1) {
            accB[s] += __shfl_down_sync(0xFFFFFFFFu, accB[s], o);
            accC[s] += __shfl_down_sync(0xFFFFFFFFu, accC[s], o);
        }
    }
    __shared__ float redB[8][16], redC[8][16];
    int warp = tid >> 5, lane = tid & 31;
    if (lane == 0) {
        #pragma unroll
        for (int s = 0; s < 16; s++) { redB[warp][s] = accB[s]; redC[warp][s] = accC[s]; }
    }
    __syncthreads();
    if (tid < 16) {
        float sb = 0.f, sc = 0.f;
        #pragma unroll
        for (int w = 0; w < 8; w++) { sb += redB[w][tid]; sc += redC[w][tid]; }
        g_B[t * DSTATE + tid] = sb;
        g_C[t * DSTATE + tid] = sc;
    }
}

// decay = exp(-softplus(A)) = sigmoid(-A)
__global__ void decay_kernel(const float* __restrict__ A)
{
    int s = threadIdx.x;
    if (s < DSTATE) g_decay[s] = 1.f / (1.f + expf(A[s]));
}

// local scans per (batch, chunk) with zero init; store local states + chunk end
__global__ void scan_local_kernel()
{
    int blk = blockIdx.x;
    int b = blk / NCHUNK, c = blk % NCHUNK;
    int s = threadIdx.x;
    if (s >= DSTATE) return;
    float d = g_decay[s];
    size_t base = ((size_t)b * SEQ + (size_t)c * CHUNK) * DSTATE;
    float S = 0.f;
    for (int t = 0; t < CHUNK; t++) {
        S = S * d + g_B[base + t * DSTATE + s];
        g_loc[base + t * DSTATE + s] = S;
    }
    g_E[(b * NCHUNK + c) * DSTATE + s] = S;
}

// cross-chunk carry prefix (true state at the end of the previous chunk)
__global__ void scan_carry_kernel()
{
    int id = threadIdx.x;
    if (id >= BATCH * DSTATE) return;
    int b = id / DSTATE, s = id % DSTATE;
    float d = g_decay[s];
    float d128 = powf(d, (float)CHUNK);
    float S = 0.f;
    for (int c = 0; c < NCHUNK; c++) {
        g_Sinit[(b * NCHUNK + c) * DSTATE + s] = S;
        S = S * d128 + g_E[(b * NCHUNK + c) * DSTATE + s];
    }
}

// ys[t] = sum_s C[t,s] * (loc[t,s] + d^(tl+1) * Sinit)
__global__ __launch_bounds__(CHUNK) void scan_output_kernel()
{
    int blk = blockIdx.x;
    int b = blk / NCHUNK, c = blk % NCHUNK;
    int tl = threadIdx.x;
    int t = b * SEQ + c * CHUNK + tl;

    __shared__ float sinit[DSTATE], dec[DSTATE];
    if (tl < DSTATE) {
        sinit[tl] = g_Sinit[(b * NCHUNK + c) * DSTATE + tl];
        dec[tl] = g_decay[tl];
    }
    __syncthreads();

    float ys = 0.f;
    #pragma unroll
    for (int s = 0; s < DSTATE; s++) {
        float dp = powf(dec[s], (float)(tl + 1));
        float st = g_loc[(size_t)t * DSTATE + s] + dp * sinit[s];
        ys += st * g_C[(size_t)t * DSTATE + s];
    }
    g_ys[t] = ys;
}

// y = (ys + xc*D) * silu_res
__global__ __launch_bounds__(256) void gate_kernel(const float* __restrict__ Dp)
{
    size_t i4 = (size_t)blockIdx.x * blockDim.x + threadIdx.x;
    if (i4 >= (size_t)NTOK * DINNER / 4) return;
    size_t i = i4 * 4;
    int tok = (int)(i / DINNER);
    int ch = (int)(i % DINNER);
    float ys = g_ys[tok];
    float4 xc = *(const float4*)&g_xc[i];
    float4 sr = *(const float4*)&g_sres[i];
    float4 dd = *(const float4*)&Dp[ch];
    float4 r;
    r.x = (ys + xc.x * dd.x) * sr.x;
    r.y = (ys + xc.y * dd.y) * sr.y;
    r.z = (ys + xc.z * dd.z) * sr.z;
    r.w = (ys + xc.w * dd.w) * sr.w;
    *(float4*)&g_y[i] = r;
}

// ============================================================================
extern "C" void kernel_launch(void* const* d_in, const int* in_sizes, int n_in,
                              void* d_out, int out_size)
{
    const float* x      = (const float*)d_in[0];
    const float* W_in   = (const float*)d_in[1];
    const float* conv_w = (const float*)d_in[2];
    const float* conv_b = (const float*)d_in[3];
    const float* W_B    = (const float*)d_in[4];
    const float* W_C    = (const float*)d_in[5];
    const float* A      = (const float*)d_in[6];
    const float* Dp     = (const float*)d_in[7];
    const float* W_out  = (const float*)d_in[8];
    float* out = (float*)d_out;

    // GEMM1: [16384,1024] @ [1024,4096] -> split epilogue
    {
        dim3 grid((2 * DINNER) / 128, NTOK / 128);
        sgemm_kernel<0><<<grid, 256>>>(x, W_in, nullptr, NTOK, 2 * DINNER, DMODEL);
    }

    // conv + silu + B/C projection
    conv_proj_kernel<<<NTOK, 256>>>(conv_w, conv_b, W_B, W_C);

    // scan
    decay_kernel<<<1, 32>>>(A);
    scan_local_kernel<<<BATCH * NCHUNK, 32>>>();
    scan_carry_kernel<<<1, 64>>>();
    scan_output_kernel<<<BATCH * NCHUNK, CHUNK>>>();

    // gate
    {
        size_t n4 = (size_t)NTOK * DINNER / 4;
        gate_kernel<<<(unsigned)((n4 + 255) / 256), 256>>>(Dp);
    }

    // GEMM2: [16384,2048] @ [2048,1024] -> out
    {
        dim3 grid(DMODEL / 128, NTOK / 128);
        sgemm_kernel<1><<<grid, 256>>>(nullptr, W_out, out, NTOK, DMODEL, DINNER);
    }
}

// round 2
// speedup vs baseline: 2.5119x; 2.5119x over previous
#include <cuda_runtime.h>
#include <math.h>
#include <stdint.h>

#define BATCH  4
#define SEQ    4096
#define DMODEL 1024
#define DINNER 2048
#define DSTATE 16
#define NTOK   (BATCH*SEQ)     // 16384
#define CHUNK  128
#define NCHUNK (SEQ/CHUNK)     // 32

// ---- scratch (device globals; no allocations allowed) ----
__device__ float g_xmain[(size_t)NTOK*DINNER];
__device__ float g_sres [(size_t)NTOK*DINNER];
__device__ float g_xc   [(size_t)NTOK*DINNER];
__device__ float g_y    [(size_t)NTOK*DINNER];
__device__ float g_B    [NTOK*DSTATE];
__device__ float g_C    [NTOK*DSTATE];
__device__ float g_loc  [NTOK*DSTATE];
__device__ float g_E    [BATCH*NCHUNK*DSTATE];
__device__ float g_Sinit[BATCH*NCHUNK*DSTATE];
__device__ float g_ys   [NTOK];
__device__ float g_decay[DSTATE];

__device__ __forceinline__ float silu(float v) { return v / (1.f + expf(-v)); }

// ============================================================================
// TF32 tensor-core GEMM. 128x128x32 CTA tile, 8 warps (2x4), warp tile 64x32,
// mma.sync.m16n8k8.tf32, cp.async double buffer.
// MODE 0: A = x, C split -> g_xmain / g_sres (silu)
// MODE 1: A = g_y, C -> Cp
// ============================================================================
#define BM 128
#define BN 128
#define BKK 32
#define PADA 36    // BKK + 4  (A stored [m][PADA])
#define PADB 132   // BN + 4   (B stored [k][PADB])
#define GEMM_SMEM ((2*BM*PADA + 2*BKK*PADB)*4)

__device__ __forceinline__ void cp16(void* smem, const void* gmem) {
    uint32_t s = (uint32_t)__cvta_generic_to_shared(smem);
    asm volatile("cp.async.cg.shared.global [%0], [%1], 16;" :: "r"(s), "l"(gmem));
}
__device__ __forceinline__ uint32_t f2tf(float x) {
    uint32_t r; asm("cvt.rna.tf32.f32 %0, %1;" : "=r"(r) : "f"(x)); return r;
}
__device__ __forceinline__ void mma_tf32(float* c, const uint32_t* a, const uint32_t* b) {
    asm volatile("mma.sync.aligned.m16n8k8.row.col.f32.tf32.tf32.f32 "
        "{%0,%1,%2,%3}, {%4,%5,%6,%7}, {%8,%9}, {%0,%1,%2,%3};"
        : "+f"(c[0]), "+f"(c[1]), "+f"(c[2]), "+f"(c[3])
        : "r"(a[0]), "r"(a[1]), "r"(a[2]), "r"(a[3]), "r"(b[0]), "r"(b[1]));
}

template<int MODE>
__global__ __launch_bounds__(256) void tc_gemm(
    const float* __restrict__ Ap, const float* __restrict__ Bm,
    float* __restrict__ Cp, int M, int N, int K)
{
    extern __shared__ float sm[];
    float* As = sm;                   // [2][BM][PADA]
    float* Bs = sm + 2*BM*PADA;       // [2][BKK][PADB]

    const float* A = (MODE == 1) ? (const float*)g_y : Ap;

    const int tid = threadIdx.x;
    const int bx = blockIdx.x, by = blockIdx.y;
    const int warp = tid >> 5, lane = tid & 31;
    const int wm = warp & 1, wn = warp >> 1;
    const int gid = lane >> 2, tig = lane & 3;

    const float* Ablk = A + (size_t)by * BM * K;
    const float* Bblk = Bm + bx * BN;

    float acc[4][4][4];
    #pragma unroll
    for (int i = 0; i < 4; i++)
        #pragma unroll
        for (int j = 0; j < 4; j++)
            #pragma unroll
            for (int q = 0; q < 4; q++) acc[i][j][q] = 0.f;

    // ---- prefetch helper (stage st, k offset kt) ----
    auto prefetch = [&](int st, int kt) {
        float* Asd = As + st * BM * PADA;
        float* Bsd = Bs + st * BKK * PADB;
        #pragma unroll
        for (int i = 0; i < 4; i++) {
            int lin = tid + i * 256;           // 0..1023
            int r = lin >> 3, q = (lin & 7) * 4;
            cp16(&Asd[r * PADA + q], Ablk + (size_t)r * K + kt + q);
        }
        #pragma unroll
        for (int i = 0; i < 4; i++) {
            int lin = tid + i * 256;
            int r = lin >> 5, q = (lin & 31) * 4;
            cp16(&Bsd[r * PADB + q], Bblk + (size_t)(kt + r) * N + q);
        }
    };

    prefetch(0, 0);
    asm volatile("cp.async.commit_group;");
    asm volatile("cp.async.wait_group 0;");
    __syncthreads();

    const int NIT = K / BKK;
    for (int it = 0; it < NIT; it++) {
        int cur = it & 1;
        if (it + 1 < NIT) {
            prefetch(cur ^ 1, (it + 1) * BKK);
            asm volatile("cp.async.commit_group;");
        }

        const float* Asd = As + cur * BM * PADA + (wm * 64) * PADA;
        const float* Bsd = Bs + cur * BKK * PADB + wn * 32;

        #pragma unroll
        for (int ks = 0; ks < 4; ks++) {
            const int kb = ks * 8;
            uint32_t af[4][4], bf[4][2];
            #pragma unroll
            for (int mf = 0; mf < 4; mf++) {
                af[mf][0] = f2tf(Asd[(mf*16 + gid    ) * PADA + kb + tig    ]);
                af[mf][1] = f2tf(Asd[(mf*16 + gid + 8) * PADA + kb + tig    ]);
                af[mf][2] = f2tf(Asd[(mf*16 + gid    ) * PADA + kb + tig + 4]);
                af[mf][3] = f2tf(Asd[(mf*16 + gid + 8) * PADA + kb + tig + 4]);
            }
            #pragma unroll
            for (int nf = 0; nf < 4; nf++) {
                bf[nf][0] = f2tf(Bsd[(kb + tig    ) * PADB + nf*8 + gid]);
                bf[nf][1] = f2tf(Bsd[(kb + tig + 4) * PADB + nf*8 + gid]);
            }
            #pragma unroll
            for (int mf = 0; mf < 4; mf++)
                #pragma unroll
                for (int nf = 0; nf < 4; nf++)
                    mma_tf32(acc[mf][nf], af[mf], bf[nf]);
        }

        if (it + 1 < NIT) asm volatile("cp.async.wait_group 0;");
        __syncthreads();
    }

    // ---- epilogue ----
    const int row0 = by * BM + wm * 64;
    const int col0 = bx * BN + wn * 32;
    #pragma unroll
    for (int mf = 0; mf < 4; mf++) {
        #pragma unroll
        for (int nf = 0; nf < 4; nf++) {
            int r = row0 + mf * 16 + gid;
            int c = col0 + nf * 8 + tig * 2;
            float2 v0 = make_float2(acc[mf][nf][0], acc[mf][nf][1]);
            float2 v1 = make_float2(acc[mf][nf][2], acc[mf][nf][3]);
            if (MODE == 0) {
                if (c < DINNER) {
                    *(float2*)&g_xmain[(size_t)r * DINNER + c] = v0;
                    *(float2*)&g_xmain[(size_t)(r + 8) * DINNER + c] = v1;
                } else {
                    int c2 = c - DINNER;
                    float2 s0 = make_float2(silu(v0.x), silu(v0.y));
                    float2 s1 = make_float2(silu(v1.x), silu(v1.y));
                    *(float2*)&g_sres[(size_t)r * DINNER + c2] = s0;
                    *(float2*)&g_sres[(size_t)(r + 8) * DINNER + c2] = s1;
                }
            } else {
                *(float2*)&Cp[(size_t)r * N + c] = v0;
                *(float2*)&Cp[(size_t)(r + 8) * N + c] = v1;
            }
        }
    }
}

// ============================================================================
// Depthwise conv(3, pad 1) + bias + SiLU, then B/C projections (2048 -> 16)
// ============================================================================
__global__ __launch_bounds__(256) void conv_proj_kernel(
    const float* __restrict__ cw, const float* __restrict__ cb,
    const float* __restrict__ WB, const float* __restrict__ WC)
{
    int t = blockIdx.x;
    int l = t & (SEQ - 1);
    int tid = threadIdx.x;

    float accB[16], accC[16];
    #pragma unroll
    for (int s = 0; s < 16; s++) { accB[s] = 0.f; accC[s] = 0.f; }

    const float* xm = g_xmain + (size_t)t * DINNER;
    float* xcout = g_xc + (size_t)t * DINNER;

    for (int i = tid; i < DINNER; i += 256) {
        float w0 = cw[i * 3 + 0], w1 = cw[i * 3 + 1], w2 = cw[i * 3 + 2];
        float v = cb[i] + xm[i] * w1;
        if (l > 0)       v += xm[i - DINNER] * w0;
        if (l < SEQ - 1) v += xm[i + DINNER] * w2;
        float xc = silu(v);
        xcout[i] = xc;

        const float4* wb = (const float4*)(WB + (size_t)i * DSTATE);
        const float4* wc = (const float4*)(WC + (size_t)i * DSTATE);
        #pragma unroll
        for (int q = 0; q < 4; q++) {
            float4 b4 = wb[q], c4 = wc[q];
            accB[q * 4 + 0] += xc * b4.x;
            accB[q * 4 + 1] += xc * b4.y;
            accB[q * 4 + 2] += xc * b4.z;
            accB[q * 4 + 3] += xc * b4.w;
            accC[q * 4 + 0] += xc * c4.x;
            accC[q * 4 + 1] += xc * c4.y;
            accC[q * 4 + 2] += xc * c4.z;
            accC[q * 4 + 3] += xc * c4.w;
        }
    }

    #pragma unroll
    for (int s = 0; s < 16; s++) {
        #pragma unroll
        for (int o = 16; o > 0; o >>= 1) {
            accB[s] += __shfl_down_sync(0xFFFFFFFFu, accB[s], o);
            accC[s] += __shfl_down_sync(0xFFFFFFFFu, accC[s], o);
        }
    }
    __shared__ float redB[8][16], redC[8][16];
    int warp = tid >> 5, lane = tid & 31;
    if (lane == 0) {
        #pragma unroll
        for (int s = 0; s < 16; s++) { redB[warp][s] = accB[s]; redC[warp][s] = accC[s]; }
    }
    __syncthreads();
    if (tid < 16) {
        float sb = 0.f, sc = 0.f;
        #pragma unroll
        for (int w = 0; w < 8; w++) { sb += redB[w][tid]; sc += redC[w][tid]; }
        g_B[t * DSTATE + tid] = sb;
        g_C[t * DSTATE + tid] = sc;
    }
}

__global__ void decay_kernel(const float* __restrict__ A)
{
    int s = threadIdx.x;
    if (s < DSTATE) g_decay[s] = 1.f / (1.f + expf(A[s]));
}

__global__ void scan_local_kernel()
{
    int blk = blockIdx.x;
    int b = blk / NCHUNK, c = blk % NCHUNK;
    int s = threadIdx.x;
    if (s >= DSTATE) return;
    float d = g_decay[s];
    size_t base = ((size_t)b * SEQ + (size_t)c * CHUNK) * DSTATE;
    float S = 0.f;
    for (int t = 0; t < CHUNK; t++) {
        S = S * d + g_B[base + t * DSTATE + s];
        g_loc[base + t * DSTATE + s] = S;
    }
    g_E[(b * NCHUNK + c) * DSTATE + s] = S;
}

__global__ void scan_carry_kernel()
{
    int id = threadIdx.x;
    if (id >= BATCH * DSTATE) return;
    int b = id / DSTATE, s = id % DSTATE;
    float d = g_decay[s];
    float d128 = powf(d, (float)CHUNK);
    float S = 0.f;
    for (int c = 0; c < NCHUNK; c++) {
        g_Sinit[(b * NCHUNK + c) * DSTATE + s] = S;
        S = S * d128 + g_E[(b * NCHUNK + c) * DSTATE + s];
    }
}

__global__ __launch_bounds__(CHUNK) void scan_output_kernel()
{
    int blk = blockIdx.x;
    int b = blk / NCHUNK, c = blk % NCHUNK;
    int tl = threadIdx.x;
    int t = b * SEQ + c * CHUNK + tl;

    __shared__ float sinit[DSTATE], dec[DSTATE];
    if (tl < DSTATE) {
        sinit[tl] = g_Sinit[(b * NCHUNK + c) * DSTATE + tl];
        dec[tl] = g_decay[tl];
    }
    __syncthreads();

    float ys = 0.f;
    #pragma unroll
    for (int s = 0; s < DSTATE; s++) {
        float dp = powf(dec[s], (float)(tl + 1));
        float st = g_loc[(size_t)t * DSTATE + s] + dp * sinit[s];
        ys += st * g_C[(size_t)t * DSTATE + s];
    }
    g_ys[t] = ys;
}

__global__ __launch_bounds__(256) void gate_kernel(const float* __restrict__ Dp)
{
    size_t i4 = (size_t)blockIdx.x * blockDim.x + threadIdx.x;
    if (i4 >= (size_t)NTOK * DINNER / 4) return;
    size_t i = i4 * 4;
    int tok = (int)(i / DINNER);
    int ch = (int)(i % DINNER);
    float ys = g_ys[tok];
    float4 xc = *(const float4*)&g_xc[i];
    float4 sr = *(const float4*)&g_sres[i];
    float4 dd = *(const float4*)&Dp[ch];
    float4 r;
    r.x = (ys + xc.x * dd.x) * sr.x;
    r.y = (ys + xc.y * dd.y) * sr.y;
    r.z = (ys + xc.z * dd.z) * sr.z;
    r.w = (ys + xc.w * dd.w) * sr.w;
    *(float4*)&g_y[i] = r;
}

// ============================================================================
extern "C" void kernel_launch(void* const* d_in, const int* in_sizes, int n_in,
                              void* d_out, int out_size)
{
    const float* x      = (const float*)d_in[0];
    const float* W_in   = (const float*)d_in[1];
    const float* conv_w = (const float*)d_in[2];
    const float* conv_b = (const float*)d_in[3];
    const float* W_B    = (const float*)d_in[4];
    const float* W_C    = (const float*)d_in[5];
    const float* A      = (const float*)d_in[6];
    const float* Dp     = (const float*)d_in[7];
    const float* W_out  = (const float*)d_in[8];
    float* out = (float*)d_out;

    static int attr_done = 0;
    if (!attr_done) {
        cudaFuncSetAttribute(tc_gemm<0>, cudaFuncAttributeMaxDynamicSharedMemorySize, GEMM_SMEM);
        cudaFuncSetAttribute(tc_gemm<1>, cudaFuncAttributeMaxDynamicSharedMemorySize, GEMM_SMEM);
        attr_done = 1;
    }

    // GEMM1: [16384,1024] @ [1024,4096] -> split epilogue (xmain / silu(res))
    {
        dim3 grid((2 * DINNER) / BN, NTOK / BM);
        tc_gemm<0><<<grid, 256, GEMM_SMEM>>>(x, W_in, nullptr, NTOK, 2 * DINNER, DMODEL);
    }

    // conv + silu + B/C projection
    conv_proj_kernel<<<NTOK, 256>>>(conv_w, conv_b, W_B, W_C);

    // scan
    decay_kernel<<<1, 32>>>(A);
    scan_local_kernel<<<BATCH * NCHUNK, 32>>>();
    scan_carry_kernel<<<1, 64>>>();
    scan_output_kernel<<<BATCH * NCHUNK, CHUNK>>>();

    // gate
    {
        size_t n4 = (size_t)NTOK * DINNER / 4;
        gate_kernel<<<(unsigned)((n4 + 255) / 256), 256>>>(Dp);
    }

    // GEMM2: [16384,2048] @ [2048,1024] -> out
    {
        dim3 grid(DMODEL / BN, NTOK / BM);
        tc_gemm<1><<<grid, 256, GEMM_SMEM>>>(nullptr, W_out, out, NTOK, DMODEL, DINNER);
    }
}